// round 7
// baseline (speedup 1.0000x reference)
#include <cuda_runtime.h>
#include <math.h>

#define NB 32
#define NC 256
#define NH 64
#define NW 64
#define HW (NH*NW)          // 4096
#define HW4 (HW/4)          // 1024 float4 groups per (b,c) plane
#define KS 7
#define PAD 3

#define CHUNK 16            // images per chunk (64 MiB, fits 126MB L2)

// partial stats: [half][b][hw]  (half 0 = ch 0..127, half 1 = ch 128..255)
__device__ float g_pmax[2 * NB * HW];
__device__ float g_psum[2 * NB * HW];
__device__ float g_scale[NB * HW];       // sigmoid(conv)

// ---------------------------------------------------------------------------
// reduce job: one block = 32 float4-pixel-groups x 16 channel-splits x 1 half.
// rbid in [0, 1024) per chunk: pairid = rbid>>1 selects pixel groups,
// half = rbid&1 selects channels [half*128, half*128+128). 8 ch per thread.
// ---------------------------------------------------------------------------
__device__ __forceinline__ void reduce_block(const float* __restrict__ x,
                                             int b0, int rbid, int tid)
{
    __shared__ float4 s_max[16][32];
    __shared__ float4 s_sum[16][32];

    int pix = tid & 31;
    int cs  = tid >> 5;               // 0..15
    int pairid = rbid >> 1;
    int half   = rbid & 1;

    int gp = pairid * 32 + pix;       // chunk-local f4 group
    int b  = b0 + (gp >> 10);
    int g  = gp & 1023;

    const float4* xb = reinterpret_cast<const float4*>(x)
                     + ((size_t)b * NC + half * 128 + cs * 8) * HW4 + g;

    float4 mx = make_float4(-INFINITY, -INFINITY, -INFINITY, -INFINITY);
    float4 sm = make_float4(0.f, 0.f, 0.f, 0.f);

    #pragma unroll
    for (int c = 0; c < 8; c++) {
        float4 v = __ldg(xb + c * HW4);
        mx.x = fmaxf(mx.x, v.x);  sm.x += v.x;
        mx.y = fmaxf(mx.y, v.y);  sm.y += v.y;
        mx.z = fmaxf(mx.z, v.z);  sm.z += v.z;
        mx.w = fmaxf(mx.w, v.w);  sm.w += v.w;
    }

    s_max[cs][pix] = mx;
    s_sum[cs][pix] = sm;
    __syncthreads();

    if (cs == 0) {
        #pragma unroll
        for (int k = 1; k < 16; k++) {
            float4 m = s_max[k][pix];
            float4 s = s_sum[k][pix];
            mx.x = fmaxf(mx.x, m.x);  sm.x += s.x;
            mx.y = fmaxf(mx.y, m.y);  sm.y += s.y;
            mx.z = fmaxf(mx.z, m.z);  sm.z += s.z;
            mx.w = fmaxf(mx.w, m.w);  sm.w += s.w;
        }
        size_t o = ((size_t)half * NB + b) * HW4 + g;
        reinterpret_cast<float4*>(g_pmax)[o] = mx;
        reinterpret_cast<float4*>(g_psum)[o] = sm;
    }
}

// ---------------------------------------------------------------------------
// scale job: out = x * scale.  sbid in [0, 1024) per chunk, 512 threads.
// chunk-local idx bits: [b:4][cs:5][g:10], 8 channels per thread.
// ---------------------------------------------------------------------------
__device__ __forceinline__ void scale_block(const float* __restrict__ x,
                                            float* __restrict__ out,
                                            int b0, int sbid, int tid)
{
    int idx = sbid * 512 + tid;
    int g  = idx & 1023;
    int cs = (idx >> 10) & 31;
    int b  = b0 + (idx >> 15);

    float4 s = __ldg(reinterpret_cast<const float4*>(g_scale) + (size_t)b * HW4 + g);

    const float4* xb = reinterpret_cast<const float4*>(x)
                     + ((size_t)b * NC + cs * 8) * HW4 + g;
    float4* ob = reinterpret_cast<float4*>(out)
               + ((size_t)b * NC + cs * 8) * HW4 + g;

    #pragma unroll
    for (int c = 0; c < 8; c++) {
        float4 v = __ldcs(xb + c * HW4);   // last use of x: evict-first
        v.x *= s.x; v.y *= s.y; v.z *= s.z; v.w *= s.w;
        __stcs(ob + c * HW4, v);           // streaming store
    }
}

// ---------------------------------------------------------------------------
// Standalone kernels
// ---------------------------------------------------------------------------
__global__ void __launch_bounds__(512) reduce_kernel(const float* __restrict__ x, int b0)
{
    reduce_block(x, b0, blockIdx.x, threadIdx.x);
}

__global__ void __launch_bounds__(512) scale_kernel(const float* __restrict__ x,
                                                    float* __restrict__ out, int b0)
{
    scale_block(x, out, b0, blockIdx.x, threadIdx.x);
}

// Fused: even blocks run scale(chunk b0s), odd blocks run reduce(chunk b0r).
// Overlaps scale's DRAM writes with the next chunk's DRAM reads.
__global__ void __launch_bounds__(512) fused_kernel(const float* __restrict__ x,
                                                    float* __restrict__ out,
                                                    int b0s, int b0r)
{
    if (blockIdx.x & 1) reduce_block(x, b0r, blockIdx.x >> 1, threadIdx.x);
    else                scale_block(x, out, b0s, blockIdx.x >> 1, threadIdx.x);
}

// ---------------------------------------------------------------------------
// conv: combine partial halves into a zero-padded smem stats tile, 7x7 conv,
// sigmoid -> g_scale. One block = one 8-row strip of one image. 128 threads.
// ---------------------------------------------------------------------------
#define TW 72   // 64 + 2*3 padding + 2 slack (keeps rows 8B-aligned-ish)
__global__ void __launch_bounds__(128) conv_kernel(const float* __restrict__ wgt, int b0)
{
    __shared__ float sw[2 * KS * KS];
    __shared__ float st[2][14][TW];

    int tid = threadIdx.x;
    if (tid < 2 * KS * KS) sw[tid] = wgt[tid];

    int b     = b0 + (blockIdx.x >> 3);
    int strip = blockIdx.x & 7;
    int h0    = strip * 8;

    const float* pmax0 = g_pmax + (size_t)b * HW;
    const float* pmax1 = g_pmax + (size_t)(NB + b) * HW;
    const float* psum0 = g_psum + (size_t)b * HW;
    const float* psum1 = g_psum + (size_t)(NB + b) * HW;

    // fill 2 planes x 14 rows x TW cols (global col = c - 3)
    for (int i = tid; i < 2 * 14 * TW; i += 128) {
        int plane = i / (14 * TW);
        int rem   = i % (14 * TW);
        int r = rem / TW;
        int c = rem % TW;
        int gr = h0 - PAD + r;
        int gc = c - PAD;
        float v = 0.f;
        if (gr >= 0 && gr < NH && gc >= 0 && gc < NW) {
            int off = gr * NW + gc;
            v = (plane == 0) ? fmaxf(__ldg(pmax0 + off), __ldg(pmax1 + off))
                             : (__ldg(psum0 + off) + __ldg(psum1 + off)) * (1.0f / (float)NC);
        }
        st[plane][r][c] = v;
    }
    __syncthreads();

    int h_l = tid >> 4;               // 0..7
    int w0  = (tid & 15) << 2;        // 0,4,..60

    float acc0 = 0.f, acc1 = 0.f, acc2 = 0.f, acc3 = 0.f;
    #pragma unroll
    for (int kh = 0; kh < KS; kh++) {
        #pragma unroll
        for (int kw = 0; kw < KS; kw++) {
            float wm = sw[kh * KS + kw];
            float wa = sw[KS * KS + kh * KS + kw];
            int r = h_l + kh;
            int c = w0 + kw;          // already includes -PAD via tile offset
            acc0 += st[0][r][c    ] * wm + st[1][r][c    ] * wa;
            acc1 += st[0][r][c + 1] * wm + st[1][r][c + 1] * wa;
            acc2 += st[0][r][c + 2] * wm + st[1][r][c + 2] * wa;
            acc3 += st[0][r][c + 3] * wm + st[1][r][c + 3] * wa;
        }
    }

    float4 s;
    s.x = 1.0f / (1.0f + __expf(-acc0));
    s.y = 1.0f / (1.0f + __expf(-acc1));
    s.z = 1.0f / (1.0f + __expf(-acc2));
    s.w = 1.0f / (1.0f + __expf(-acc3));

    reinterpret_cast<float4*>(g_scale)[(size_t)b * HW4 + (h0 + h_l) * 16 + (w0 >> 2)] = s;
}

extern "C" void kernel_launch(void* const* d_in, const int* in_sizes, int n_in,
                              void* d_out, int out_size)
{
    const float* x = (const float*)d_in[0];
    const float* w = (const float*)d_in[1];
    float* out = (float*)d_out;

    // chunk 0: images 0..15, chunk 1: images 16..31
    reduce_kernel<<<1024, 512>>>(x, 0);
    conv_kernel<<<CHUNK * 8, 128>>>(w, 0);
    fused_kernel<<<2048, 512>>>(x, out, 0, CHUNK);   // scale(c0) || reduce(c1)
    conv_kernel<<<CHUNK * 8, 128>>>(w, CHUNK);
    scale_kernel<<<1024, 512>>>(x, out, CHUNK);
}